// round 12
// baseline (speedup 1.0000x reference)
#include <cuda_runtime.h>
#include <cuda_bf16.h>
#include <math_constants.h>

#define BATCH 64
#define SEQ   256
#define TCH   16
#define VOC   262
#define EMB   64
#define HID   32
#define G3    96
#define NSEQ  (BATCH*SEQ)

// Tables (device globals — no allocation allowed)
// Permuted GI rows: pos(gate,j) = gate*32 + tig*8 + hg*2 + e
// r,z entries pre-scaled by 0.5 (sigmoid-via-tanh); bhh folded for r,z.
__device__ __align__(128) float g_GI2[2 * VOC * G3];
// Pre-packed bf16 B fragments (m16n8k16): [dir][nb][kc][lane] = uint2(b0,b1)
// nb<8 rows pre-scaled 0.5.
__device__ uint2 g_WF[2 * 12 * 2 * 32];

__device__ __forceinline__ unsigned packbf(float lo, float hi) {
    unsigned d;
    asm("cvt.rn.bf16x2.f32 %0, %1, %2;" : "=r"(d) : "f"(hi), "f"(lo));
    return d;
}
__device__ __forceinline__ float tanhapx(float x) {
    float r;
    asm("tanh.approx.f32 %0, %1;" : "=f"(r) : "f"(x));
    return r;
}
// MMA with accumulators on four independent float lvalues (in-place)
__device__ __forceinline__ void mma4(float& d0, float& d1, float& d2, float& d3,
                                     const unsigned* a, unsigned b0, unsigned b1) {
    asm("mma.sync.aligned.m16n8k16.row.col.f32.bf16.bf16.f32 "
        "{%0,%1,%2,%3}, {%4,%5,%6,%7}, {%8,%9}, {%0,%1,%2,%3};"
        : "+f"(d0), "+f"(d1), "+f"(d2), "+f"(d3)
        : "r"(a[0]), "r"(a[1]), "r"(a[2]), "r"(a[3]), "r"(b0), "r"(b1));
}
__device__ __forceinline__ float& f4c(float4& v, int c) {
    return c == 0 ? v.x : c == 1 ? v.y : c == 2 ? v.z : v.w;
}

// ---------------------------------------------------------------------------
// Kernel 1: GI tables + bf16 B-fragment pack. grid = VOC+1, block = 192.
// ---------------------------------------------------------------------------
__global__ void build_tables(const float* __restrict__ emb,
                             const float* __restrict__ Wih_f,
                             const float* __restrict__ bih_f,
                             const float* __restrict__ bhh_f,
                             const float* __restrict__ Wih_b,
                             const float* __restrict__ bih_b,
                             const float* __restrict__ bhh_b,
                             const float* __restrict__ Whh_f,
                             const float* __restrict__ Whh_b) {
    int c   = blockIdx.x;
    int tid = threadIdx.x;
    if (c < VOC) {
        int dir = tid / 96;
        int g   = tid % 96;
        __shared__ float e[EMB];
        if (tid < EMB) e[tid] = emb[c * EMB + tid];
        __syncthreads();
        const float* Wih = dir ? Wih_b : Wih_f;
        const float* bih = dir ? bih_b : bih_f;
        const float* bhh = dir ? bhh_b : bhh_f;
        float a0 = bih[g] + (g < 64 ? bhh[g] : 0.0f);
        float a1 = 0.0f;
        const float4* wr4 = (const float4*)(Wih + g * EMB);
        #pragma unroll
        for (int k4 = 0; k4 < EMB / 4; k4++) {
            float4 wv = wr4[k4];
            a0 = fmaf(wv.x, e[4 * k4],     a0);
            a1 = fmaf(wv.y, e[4 * k4 + 1], a1);
            a0 = fmaf(wv.z, e[4 * k4 + 2], a0);
            a1 = fmaf(wv.w, e[4 * k4 + 3], a1);
        }
        float v = a0 + a1;
        if (g < 64) v *= 0.5f;               // sigmoid-via-tanh prescale
        int gate = g >> 5, j = g & 31;
        int hg = j >> 3, tg = (j >> 1) & 3, eb = j & 1;
        int pos = gate * 32 + tg * 8 + hg * 2 + eb;
        g_GI2[dir * (VOC * G3) + c * G3 + pos] = v;
    } else {
        for (int i = tid; i < 1536; i += 192) {
            int d    = i / 768;
            int rem  = i % 768;
            int nb   = rem / 64;
            int kc   = (rem / 32) & 1;
            int lane = rem & 31;
            int gid = lane >> 2, tg = lane & 3;
            const float* W = d ? Whh_b : Whh_f;
            const float* row = W + (8 * nb + gid) * HID;
            float s = (nb < 8) ? 0.5f : 1.0f;    // r,z rows prescaled
            int k0 = 16 * kc + 2 * tg;
            g_WF[i] = make_uint2(packbf(s * row[k0],     s * row[k0 + 1]),
                                 packbf(s * row[k0 + 8], s * row[k0 + 9]));
        }
    }
}

// ---------------------------------------------------------------------------
// Kernel 2: bf16 tensor-core GRU, MUFU-saturating occupancy.
// 512 blocks x 128 thr (4 warps), 4 blocks/SM -> single wave, 2048 resident
// warps (~3.5/SMSP). One warp = one 16-seq task. Synchronous gi loads
// (latency hidden by cross-warp MUFU work), in-place MMA accumulators,
// B fragments in smem. Blocks dir-uniform: dir = blockIdx.x >> 8.
// ---------------------------------------------------------------------------
__global__ __launch_bounds__(128, 4)
void gru_mma(const int* __restrict__ x,
             const float* __restrict__ bhh_f,
             const float* __restrict__ bhh_b,
             float* __restrict__ out) {
    __shared__ uint2 s_bf[12 * 2 * 32];     // 6 KB B fragments (dir-uniform)

    int tid  = threadIdx.x;
    int wb   = tid >> 5;
    int lane = tid & 31;
    int gid  = lane >> 2;
    int tig  = lane & 3;
    int dir  = blockIdx.x >> 8;                 // block-uniform
    int wi   = (blockIdx.x & 255) * 4 + wb;     // 0..1023
    int seq0 = wi << 4;

    {
        const uint2* src = g_WF + dir * 768;
        #pragma unroll
        for (int i = 0; i < 6; i++)
            s_bf[tid + 128 * i] = src[tid + 128 * i];
    }
    __syncthreads();

    const float* __restrict__ GI  = g_GI2 + dir * (VOC * G3);
    const float* __restrict__ bhh = dir ? bhh_b : bhh_f;

    float bnlo[4], bnhi[4];
    #pragma unroll
    for (int hg = 0; hg < 4; hg++) {
        bnlo[hg] = bhh[64 + 8 * hg + 2 * tig];
        bnhi[hg] = bhh[64 + 8 * hg + 2 * tig + 1];
    }

    const int* xA = x + (seq0 + gid) * TCH;
    const int* xB = x + (seq0 + gid + 8) * TCH;

    float hn[4][4], hmax[4][4];
    #pragma unroll
    for (int hg = 0; hg < 4; hg++)
        #pragma unroll
        for (int s = 0; s < 4; s++) { hn[hg][s] = 0.0f; hmax[hg][s] = -CUDART_INF_F; }

    // T(k) = dir ? 15-k : k  (masked to stay in-bounds on overrun)
    #define TIDX(k) (dir ? ((TCH - 1 - (k)) & (TCH - 1)) : ((k) & (TCH - 1)))

    int cA  = xA[TIDX(0)], cB  = xB[TIDX(0)];
    int cAn = xA[TIDX(1)], cBn = xB[TIDX(1)];

    #pragma unroll 1
    for (int tt = 0; tt < TCH; ++tt) {
        // --- gi for this step (synchronous; latency hidden by other warps) ---
        float4 cur[12];
        {
            const float4* pA4 = (const float4*)(GI + cA * G3);
            const float4* pB4 = (const float4*)(GI + cB * G3);
            cur[0]  = pA4[tig * 2];      cur[1]  = pA4[tig * 2 + 1];
            cur[2]  = pA4[8 + tig * 2];  cur[3]  = pA4[8 + tig * 2 + 1];
            cur[4]  = pA4[16 + tig * 2]; cur[5]  = pA4[16 + tig * 2 + 1];
            cur[6]  = pB4[tig * 2];      cur[7]  = pB4[tig * 2 + 1];
            cur[8]  = pB4[8 + tig * 2];  cur[9]  = pB4[8 + tig * 2 + 1];
            cur[10] = pB4[16 + tig * 2]; cur[11] = pB4[16 + tig * 2 + 1];
        }

        // rotate char indices; prefetch for step tt+2
        cA = cAn; cB = cBn;
        int tn2 = TIDX(tt + 2);
        cAn = xA[tn2]; cBn = xB[tn2];

        // pack A fragments (lane-local bf16)
        unsigned a[2][4];
        #pragma unroll
        for (int kc = 0; kc < 2; kc++) {
            a[kc][0] = packbf(hn[2 * kc][0],     hn[2 * kc][1]);
            a[kc][1] = packbf(hn[2 * kc][2],     hn[2 * kc][3]);
            a[kc][2] = packbf(hn[2 * kc + 1][0], hn[2 * kc + 1][1]);
            a[kc][3] = packbf(hn[2 * kc + 1][2], hn[2 * kc + 1][3]);
        }

        // n-gate accumulators start at recurrent bias
        float nacc[4][4];
        #pragma unroll
        for (int hg = 0; hg < 4; hg++) {
            nacc[hg][0] = bnlo[hg]; nacc[hg][1] = bnhi[hg];
            nacc[hg][2] = bnlo[hg]; nacc[hg][3] = bnhi[hg];
        }

        // 24 MMAs: r,z accumulate IN-PLACE into cur; n into nacc
        #pragma unroll
        for (int kc = 0; kc < 2; kc++) {
            #pragma unroll
            for (int m = 0; m < 4; m++) {
                int bi = m >> 1;
                int c0 = (m & 1) * 2;
                uint2 br = s_bf[(m * 2 + kc) * 32 + lane];
                mma4(f4c(cur[bi], c0),     f4c(cur[bi], c0 + 1),
                     f4c(cur[6 + bi], c0), f4c(cur[6 + bi], c0 + 1),
                     a[kc], br.x, br.y);
                uint2 bz = s_bf[((4 + m) * 2 + kc) * 32 + lane];
                mma4(f4c(cur[2 + bi], c0), f4c(cur[2 + bi], c0 + 1),
                     f4c(cur[8 + bi], c0), f4c(cur[8 + bi], c0 + 1),
                     a[kc], bz.x, bz.y);
                uint2 bnf = s_bf[((8 + m) * 2 + kc) * 32 + lane];
                mma4(nacc[m][0], nacc[m][1], nacc[m][2], nacc[m][3],
                     a[kc], bnf.x, bnf.y);
            }
        }

        // activations read gate pre-activations directly from cur
        #pragma unroll
        for (int hg = 0; hg < 4; hg++)
            #pragma unroll
            for (int s = 0; s < 4; s++) {
                int bi = (s >> 1) * 6 + (hg >> 1);
                int c  = (hg & 1) * 2 + (s & 1);
                float r = fmaf(tanhapx(f4c(cur[bi], c)),     0.5f, 0.5f);
                float z = fmaf(tanhapx(f4c(cur[2 + bi], c)), 0.5f, 0.5f);
                float n = tanhapx(fmaf(r, nacc[hg][s], f4c(cur[4 + bi], c)));
                float h = fmaf(z, hn[hg][s] - n, n);
                hn[hg][s] = h;
                hmax[hg][s] = fmaxf(hmax[hg][s], h);
            }
    }
    #undef TIDX

    int sA = seq0 + gid, sB = seq0 + gid + 8;
    #pragma unroll
    for (int hg = 0; hg < 4; hg++) {
        int col = 8 * hg + 2 * tig;
        *(float2*)(out + sA * 64 + dir * 32 + col) = make_float2(hmax[hg][0], hmax[hg][1]);
        *(float2*)(out + sB * 64 + dir * 32 + col) = make_float2(hmax[hg][2], hmax[hg][3]);
    }
}

// ---------------------------------------------------------------------------
// kernel_launch
// ---------------------------------------------------------------------------
extern "C" void kernel_launch(void* const* d_in, const int* in_sizes, int n_in,
                              void* d_out, int out_size) {
    const int*   x     = (const int*)  d_in[0];
    const float* emb   = (const float*)d_in[1];
    const float* Wih_f = (const float*)d_in[2];
    const float* Whh_f = (const float*)d_in[3];
    const float* bih_f = (const float*)d_in[4];
    const float* bhh_f = (const float*)d_in[5];
    const float* Wih_b = (const float*)d_in[6];
    const float* Whh_b = (const float*)d_in[7];
    const float* bih_b = (const float*)d_in[8];
    const float* bhh_b = (const float*)d_in[9];
    float* out = (float*)d_out;

    build_tables<<<VOC + 1, 192>>>(emb, Wih_f, bih_f, bhh_f,
                                   Wih_b, bih_b, bhh_b, Whh_f, Whh_b);

    // 512 blocks x 4 warps = 2048 warps, one 16-seq task each.
    // 4 blocks/SM capacity -> single wave, ~14 resident warps/SM.
    gru_mma<<<512, 128>>>(x, bhh_f, bhh_b, out);
}